// round 6
// baseline (speedup 1.0000x reference)
#include <cuda_runtime.h>

// EdgeBlock: windowed attention-ish scoring + value gather.
// Shapes fixed by the problem: B=4, L=1024, N=16, D=64, W=16, V=33.
//
// Outputs (concatenated in d_out, fp32):
//   window_score: (B, N, L, V)        = 2,162,688 floats
//   value_h:      (B, L, V, N, D)     = 138,412,032 floats   <-- 553 MB, dominates
//
// off_u[v] = 0 for v<=W, v-W for v>W      (so idx_u = l + off_u, mod L)
// off_d[v] = v-W for v<W, 0 for v>=W      (so idx_d = l + off_d, mod L)
// indices_mask = (l+off_d >= 0) && (l+off_u < L)   [pre-mod]
// score = leaky_relu(upon_s[idx_u] + down_s[idx_d] + qc . hidden[idx_u], slope=5)
// window_score = m ? score : -1e12 ;  m = mask[b, idx_u] & indices_mask
//
// NOTE: mask is int32 on the wire (bool -> int32), NOT bytes. Reading it as
// bytes produced rel_err 9.616 == sqrt(0.744/0.00805), the exact signature of
// 75% spurious masking from reading the 01 00 00 00 little-endian pattern.

#define Bc 4
#define Lc 1024
#define Nc 16
#define Dc 64
#define Wc 16
#define Vc 33
#define NDc (Nc*Dc)          // 1024 floats per (b,l) row
#define NDc4 (NDc/4)         // 256 float4

// ---------------------------------------------------------------------------
// Score kernel: one block per (b, n, 128-l tile). 256 threads = 8 warps.
// SMEM: cross[n] (64x64), 160 hidden rows (l0-16 .. l0+143, wrapped) with
// row stride 65 (conflict-free strided row reads), per-row upon/down dots,
// per-warp qc buffer.
// ---------------------------------------------------------------------------
__global__ void score_kernel(const float* __restrict__ hidden,
                             const int* __restrict__ mask,
                             const float* __restrict__ upon,
                             const float* __restrict__ down,
                             const float* __restrict__ cross,
                             float* __restrict__ out_ws) {
    extern __shared__ float sm[];
    float* sh_cross = sm;                 // 4096   (d-major: sh_cross[d*64+h])
    float* shH      = sm + 4096;          // 160*65 = 10400
    float* su       = shH + 160*65;       // 160
    float* sd       = su + 160;           // 160
    float* sh_up    = sd + 160;           // 64
    float* sh_dn    = sh_up + 64;         // 64
    float* qc_sm    = sh_dn + 64;         // 8*64 = 512

    const int t  = threadIdx.x;           // 0..255
    const int n  = blockIdx.y;
    const int b  = blockIdx.z;
    const int l0 = blockIdx.x * 128;

    for (int i = t; i < 4096; i += 256)
        sh_cross[i] = cross[n * 4096 + i];
    if (t < 64) {
        sh_up[t] = upon[n * 64 + t];
        sh_dn[t] = down[n * 64 + t];
    }
    // 160 rows: local r corresponds to global row (l0 - 16 + r) mod L
    for (int i = t; i < 160 * 64; i += 256) {
        int r = i >> 6, d = i & 63;
        int row = (l0 - Wc + r + Lc) & (Lc - 1);
        shH[r * 65 + d] = hidden[(((size_t)b * Lc + row) * Nc + n) * Dc + d];
    }
    __syncthreads();

    // per-row projection dots (threads 0..159, conflict-free: stride-65 rows)
    if (t < 160) {
        const float* hr = &shH[t * 65];
        float a = 0.f, c = 0.f;
#pragma unroll
        for (int d = 0; d < 64; ++d) { a += hr[d] * sh_up[d]; c += hr[d] * sh_dn[d]; }
        su[t] = a; sd[t] = c;
    }
    __syncthreads();

    const int w = t >> 5, lane = t & 31;
    for (int it = 0; it < 16; ++it) {
        const int lloc  = it * 8 + w;       // 0..127
        const int l     = l0 + lloc;
        const int rbase = lloc + Wc;        // local row of l
        const float* hrow = &shH[rbase * 65];

        // qc[h] = sum_d h[d] * cross[n][d][h]; lane owns h=lane and h=lane+32
        float qc0 = 0.f, qc1 = 0.f;
#pragma unroll
        for (int d = 0; d < 64; ++d) {
            float hd = hrow[d];
            qc0 += hd * sh_cross[d * 64 + lane];
            qc1 += hd * sh_cross[d * 64 + lane + 32];
        }
        qc_sm[w * 64 + lane]      = qc0;
        qc_sm[w * 64 + lane + 32] = qc1;
        __syncwarp();

        const float* qv = &qc_sm[w * 64];
#pragma unroll
        for (int vi = 0; vi < 2; ++vi) {
            int v = lane + vi * 32;         // lane 0 also handles v=32
            if (v < Vc) {
                int offu = (v <= Wc) ? 0 : (v - Wc);
                int offd = (v <  Wc) ? (v - Wc) : 0;
                int ru = rbase + offu;
                const float* hv = &shH[ru * 65];
                float prod = 0.f;
#pragma unroll
                for (int h = 0; h < 64; ++h) prod += qv[h] * hv[h];
                float sc = prod + su[ru] + sd[rbase + offd];
                sc = (sc > 0.f) ? sc : 5.0f * sc;           // leaky_relu slope 5
                int iu = l + offu, id = l + offd;
                bool m = (id >= 0) && (iu < Lc) &&
                         (mask[b * Lc + (iu & (Lc - 1))] != 0);
                out_ws[((size_t)(b * Nc + n) * Lc + l) * Vc + v] = m ? sc : -1e12f;
            }
        }
        __syncwarp();  // qc_sm reused next iteration
    }
}

// ---------------------------------------------------------------------------
// Value gather: one block per (b, 8-l tile). Stage 24 source rows (96 KB) in
// SMEM, then stream 8*33 destination rows (1 MB) out. Each hidden row hits L2
// ~3x instead of 33x; DRAM-write bound.
// ---------------------------------------------------------------------------
__global__ void value_kernel(const float4* __restrict__ hidden4,
                             float4* __restrict__ out4) {
    extern __shared__ float4 sh4[];       // 24 * 256 float4 = 96 KB
    const int t  = threadIdx.x;           // 256
    const int b  = blockIdx.y;
    const int l0 = blockIdx.x * 8;

#pragma unroll
    for (int r = 0; r < 24; ++r) {
        int row = (l0 + r) & (Lc - 1);
        sh4[r * 256 + t] = hidden4[((size_t)b * Lc + row) * NDc4 + t];
    }
    __syncthreads();

    for (int ll = 0; ll < 8; ++ll) {
        size_t base = ((size_t)(b * Lc + l0 + ll)) * Vc * NDc4 + t;
#pragma unroll
        for (int v = 0; v < Vc; ++v) {
            int off = (v <= Wc) ? 0 : (v - Wc);
            out4[base + (size_t)v * NDc4] = sh4[(ll + off) * 256 + t];
        }
    }
}

extern "C" void kernel_launch(void* const* d_in, const int* in_sizes, int n_in,
                              void* d_out, int out_size) {
    const float* hidden = (const float*)d_in[0];
    const int*   mask   = (const int*)d_in[1];      // bool -> int32 on the wire
    const float* upon   = (const float*)d_in[2];
    const float* down   = (const float*)d_in[3];
    const float* cross  = (const float*)d_in[4];
    // d_in[5] (window_size) fixed at 16 for this problem; compiled in.

    float* out_ws  = (float*)d_out;
    float* out_val = out_ws + (size_t)Bc * Nc * Lc * Vc;   // 2,162,688 floats in

    const int smemS = (4096 + 160 * 65 + 160 + 160 + 64 + 64 + 512) * (int)sizeof(float); // 61,824 B
    const int smemV = 24 * 256 * (int)sizeof(float4);                                     // 98,304 B
    cudaFuncSetAttribute(score_kernel, cudaFuncAttributeMaxDynamicSharedMemorySize, smemS);
    cudaFuncSetAttribute(value_kernel, cudaFuncAttributeMaxDynamicSharedMemorySize, smemV);

    dim3 gs(Lc / 128, Nc, Bc);            // 8 x 16 x 4 = 512 blocks
    score_kernel<<<gs, 256, smemS>>>(hidden, mask, upon, down, cross, out_ws);

    dim3 gv(Lc / 8, Bc);                  // 128 x 4 = 512 blocks
    value_kernel<<<gv, 256, smemV>>>((const float4*)hidden, (float4*)out_val);
}

// round 7
// speedup vs baseline: 1.3700x; 1.3700x over previous
#include <cuda_runtime.h>

// EdgeBlock fused: windowed scoring + value gather, single kernel launch.
// B=4, L=1024, N=16, D=64, W=16, V=33.
//
// Outputs (concatenated fp32 in d_out):
//   window_score (B,N,L,V)    = 2,162,688 floats
//   value_h      (B,L,V,N,D)  = 138,412,032 floats (553 MB, DRAM-write bound)
//
// Block-interleaved heterogeneous grid: bid%5==0 -> score block (512 total),
// else value block (2048 total, 2-l tiles). Both paths use 73,728 B dynamic
// smem -> 3 CTAs/SM, so DRAM-bound value work overlaps smem-bound score work.
//
// Score math: off_u(v) has only 17 distinct values (0 for v<=16, v-16 after),
// so only 17 products per l are computed (lanes 0..16), then 33 outputs are
// assembled. shH/shC use row stride 68 floats: quad index (17*row + dq) % 8
// is distinct across each 8-lane LDS.128 phase -> conflict-free float4 loads.

#define Lc 1024
#define MASK_FILL -1e12f

// smem layout for score path (floats):
//   shC  [64][68]   @ 0      (cross transposed: shC[h*68+d])
//   shH  [160][68]  @ 4352   (rows l0-16 .. l0+143, wrapped)
//   su   [160]      @ 15232
//   sd   [160]      @ 15392
//   shup [64]       @ 15552
//   shdn [64]       @ 15616
//   qcs  [8][4][64] @ 15680  (per-warp qc buffer)
//   prs  [8][4][17] @ 17728  (per-warp prod buffer)
//   shm  [160] int  @ 18272
// total 18432 floats = 73728 B  (value path: 18 rows * 256 float4 = 73728 B)

__global__ void __launch_bounds__(256) fused_kernel(
    const float* __restrict__ hidden,
    const int*   __restrict__ mask,
    const float* __restrict__ upon,
    const float* __restrict__ down,
    const float* __restrict__ cross,
    float*       __restrict__ out_ws,
    float4*      __restrict__ out_val)
{
    extern __shared__ float sm[];
    const int t   = threadIdx.x;
    const int bid = blockIdx.x;
    const int s   = bid / 5;
    const int rem = bid - s * 5;

    if (rem != 0) {
        // ---------------- value path: 2-l tile, 18 staged rows ----------------
        float4* sh4 = (float4*)sm;
        const int widx = s * 4 + (rem - 1);        // 0..2047
        const int b    = widx >> 9;
        const int l0   = (widx & 511) * 2;
        const float4* hidden4 = (const float4*)hidden;

#pragma unroll
        for (int rr = 0; rr < 18; ++rr) {
            int row = (l0 + rr) & (Lc - 1);
            sh4[rr * 256 + t] = hidden4[((size_t)(b << 10) + row) * 256 + t];
        }
        __syncthreads();

#pragma unroll
        for (int ll = 0; ll < 2; ++ll) {
            size_t base = ((size_t)((b << 10) + l0 + ll)) * 33 * 256 + t;
#pragma unroll
            for (int v = 0; v < 33; ++v) {
                int off = (v <= 16) ? 0 : (v - 16);
                out_val[base + (size_t)v * 256] = sh4[(ll + off) * 256 + t];
            }
        }
        return;
    }

    // ------------------------- score path: s in 0..511 -------------------------
    const int tile = s & 7, n = (s >> 3) & 15, b = s >> 7;
    const int l0 = tile * 128;

    float* shC  = sm;             // [64][68]
    float* shH  = sm + 4352;      // [160][68]
    float* su   = sm + 15232;
    float* sd   = sm + 15392;
    float* shup = sm + 15552;
    float* shdn = sm + 15616;
    float* qcs  = sm + 15680;     // [8][4][64]
    float* prs  = sm + 17728;     // [8][4][17]
    int*   shm  = (int*)(sm + 18272);

    // cross transposed: shC[h][d] = cross[n][d][h]
    for (int i = t; i < 4096; i += 256) {
        int d2 = i >> 6, h2 = i & 63;
        shC[h2 * 68 + d2] = cross[n * 4096 + i];
    }
    if (t < 64) { shup[t] = upon[n * 64 + t]; shdn[t] = down[n * 64 + t]; }

    // shH rows l0-16 .. l0+143 (wrapped), float4 stores, stride 68
    {
        const float4* h4 = (const float4*)hidden;
        for (int i = t; i < 2560; i += 256) {         // 160 rows * 16 quads
            int rr = i >> 4, dq = i & 15;
            int row = (l0 - 16 + rr) & (Lc - 1);
            float4 v = h4[(((size_t)(b << 10) + row) * 16 + n) * 16 + dq];
            *(float4*)&shH[rr * 68 + dq * 4] = v;
        }
    }
    if (t < 160) shm[t] = mask[(b << 10) + ((l0 + t) & (Lc - 1))];
    __syncthreads();

    // per-row projection dots (float4, quad-conflict-free)
    if (t < 160) {
        const float* hr = &shH[t * 68];
        float a = 0.f, c = 0.f;
#pragma unroll
        for (int dq = 0; dq < 16; ++dq) {
            float4 hv = *(const float4*)&hr[dq * 4];
            float4 up = *(const float4*)&shup[dq * 4];
            float4 dn = *(const float4*)&shdn[dq * 4];
            a += hv.x * up.x + hv.y * up.y + hv.z * up.z + hv.w * up.w;
            c += hv.x * dn.x + hv.y * dn.y + hv.z * dn.z + hv.w * dn.w;
        }
        su[t] = a; sd[t] = c;
    }
    __syncthreads();

    const int w = t >> 5, lane = t & 31;
    float* qcw = &qcs[w * 256];
    float* prw = &prs[w * 68];

    for (int g = 0; g < 4; ++g) {
        const int lloc0 = w * 16 + g * 4;   // 4 consecutive l's per group
        const int rb    = lloc0 + 16;       // shH row of first l

        // Phase A: qc[i][h] for 4 l's; lane owns h=lane, h=lane+32.
        // cross regs reused across the 4 l's.
        float a0[4] = {0,0,0,0}, a1[4] = {0,0,0,0};
#pragma unroll
        for (int dq = 0; dq < 16; ++dq) {
            float4 c0 = *(const float4*)&shC[lane * 68 + dq * 4];
            float4 c1 = *(const float4*)&shC[(lane + 32) * 68 + dq * 4];
#pragma unroll
            for (int i = 0; i < 4; ++i) {
                float4 hd = *(const float4*)&shH[(rb + i) * 68 + dq * 4];
                a0[i] += hd.x * c0.x + hd.y * c0.y + hd.z * c0.z + hd.w * c0.w;
                a1[i] += hd.x * c1.x + hd.y * c1.y + hd.z * c1.z + hd.w * c1.w;
            }
        }
#pragma unroll
        for (int i = 0; i < 4; ++i) {
            qcw[i * 64 + lane]      = a0[i];
            qcw[i * 64 + lane + 32] = a1[i];
        }
        __syncwarp();

        // Phase B: 17 distinct window products per l (lanes 0..16)
        if (lane < 17) {
            float p[4] = {0,0,0,0};
#pragma unroll
            for (int hq = 0; hq < 16; ++hq) {
#pragma unroll
                for (int i = 0; i < 4; ++i) {
                    float4 qv = *(const float4*)&qcw[i * 64 + hq * 4];
                    float4 hv = *(const float4*)&shH[(rb + i + lane) * 68 + hq * 4];
                    p[i] += qv.x * hv.x + qv.y * hv.y + qv.z * hv.z + qv.w * hv.w;
                }
            }
#pragma unroll
            for (int i = 0; i < 4; ++i) prw[i * 17 + lane] = p[i];
        }
        __syncwarp();

        // Output: assemble 33 scores per l from 17 products
#pragma unroll
        for (int i = 0; i < 4; ++i) {
            const int lloc = lloc0 + i, l = l0 + lloc, rbl = rb + i;
            size_t obase = ((size_t)((b * 16 + n) * Lc + l)) * 33;
#pragma unroll
            for (int vi = 0; vi < 2; ++vi) {
                int v = lane + vi * 32;
                if (v < 33) {
                    int offu = (v <= 16) ? 0 : (v - 16);
                    int offd = (v <  16) ? (v - 16) : 0;
                    float sc = prw[i * 17 + offu] + su[rbl + offu] + sd[rbl + offd];
                    sc = (sc > 0.f) ? sc : 5.0f * sc;       // leaky_relu slope 5
                    bool m = (l + offd >= 0) && (l + offu < Lc) &&
                             (shm[lloc + offu] != 0);
                    out_ws[obase + v] = m ? sc : MASK_FILL;
                }
            }
        }
        __syncwarp();   // qcw/prw reused next group
    }
}

extern "C" void kernel_launch(void* const* d_in, const int* in_sizes, int n_in,
                              void* d_out, int out_size) {
    const float* hidden = (const float*)d_in[0];
    const int*   mask   = (const int*)d_in[1];      // bool -> int32 on the wire
    const float* upon   = (const float*)d_in[2];
    const float* down   = (const float*)d_in[3];
    const float* cross  = (const float*)d_in[4];
    // d_in[5] (window_size) fixed at 16; compiled in.

    float*  out_ws  = (float*)d_out;
    float4* out_val = (float4*)(out_ws + (size_t)4 * 16 * Lc * 33); // 2,162,688 floats

    const int smem = 18432 * (int)sizeof(float);    // 73,728 B (both paths)
    cudaFuncSetAttribute(fused_kernel, cudaFuncAttributeMaxDynamicSharedMemorySize, smem);

    // 2560 blocks: 512 score (bid%5==0) interleaved with 2048 value blocks
    fused_kernel<<<2560, 256, smem>>>(hidden, mask, upon, down, cross,
                                      out_ws, out_val);
}

// round 8
// speedup vs baseline: 1.4078x; 1.0276x over previous
#include <cuda_runtime.h>

// EdgeBlock fused: windowed scoring + value gather, single kernel launch.
// B=4, L=1024, N=16, D=64, W=16, V=33.
//
// Outputs (concatenated fp32 in d_out):
//   window_score (B,N,L,V)    = 2,162,688 floats
//   value_h      (B,L,V,N,D)  = 138,412,032 floats (553 MB, DRAM-write bound)
//
// Block-interleaved heterogeneous grid: bid%5==0 -> score block (512 total),
// else value block (2048 total, 2-l tiles). Both paths use 73,728 B dynamic
// smem. __launch_bounds__(256,3) caps regs at 84 so the REGISTER FILE also
// admits 3 CTAs/SM (round 7: 86 regs silently capped residency at 2 CTAs/SM
// -> DRAM stuck at 47%). 3 CTAs/SM = enough store MLP to feed HBM writes.
//
// Score math: off_u(v) has only 17 distinct values (0 for v<=16, v-16 after),
// so only 17 products per l are computed (lanes 0..16), then 33 outputs are
// assembled. shH/shC use row stride 68 floats: conflict-free LDS.128.

#define Lc 1024
#define MASK_FILL -1e12f

__global__ void __launch_bounds__(256, 3) fused_kernel(
    const float* __restrict__ hidden,
    const int*   __restrict__ mask,
    const float* __restrict__ upon,
    const float* __restrict__ down,
    const float* __restrict__ cross,
    float*       __restrict__ out_ws,
    float4*      __restrict__ out_val)
{
    extern __shared__ float sm[];
    const int t   = threadIdx.x;
    const int bid = blockIdx.x;
    const int s   = bid / 5;
    const int rem = bid - s * 5;

    if (rem != 0) {
        // ---------------- value path: 2-l tile, 18 staged rows ----------------
        float4* sh4 = (float4*)sm;
        const int widx = s * 4 + (rem - 1);        // 0..2047
        const int b    = widx >> 9;
        const int l0   = (widx & 511) * 2;
        const float4* hidden4 = (const float4*)hidden;

#pragma unroll
        for (int rr = 0; rr < 18; ++rr) {
            int row = (l0 + rr) & (Lc - 1);
            sh4[rr * 256 + t] = hidden4[((size_t)(b << 10) + row) * 256 + t];
        }
        __syncthreads();

#pragma unroll
        for (int ll = 0; ll < 2; ++ll) {
            size_t base = ((size_t)((b << 10) + l0 + ll)) * 33 * 256 + t;
#pragma unroll
            for (int v = 0; v < 33; ++v) {
                int off = (v <= 16) ? 0 : (v - 16);
                out_val[base + (size_t)v * 256] = sh4[(ll + off) * 256 + t];
            }
        }
        return;
    }

    // ------------------------- score path: s in 0..511 -------------------------
    const int tile = s & 7, n = (s >> 3) & 15, b = s >> 7;
    const int l0 = tile * 128;

    float* shC  = sm;             // [64][68]  (cross transposed: shC[h*68+d])
    float* shH  = sm + 4352;      // [160][68] (rows l0-16 .. l0+143, wrapped)
    float* su   = sm + 15232;     // [160]
    float* sd   = sm + 15392;     // [160]
    float* shup = sm + 15552;     // [64]
    float* shdn = sm + 15616;     // [64]
    float* qcs  = sm + 15680;     // [8][4][64] per-warp qc buffer
    float* prs  = sm + 17728;     // [8][4][17] per-warp prod buffer
    int*   shm  = (int*)(sm + 18272); // [160]

    // cross transposed: shC[h][d] = cross[n][d][h]
    for (int i = t; i < 4096; i += 256) {
        int d2 = i >> 6, h2 = i & 63;
        shC[h2 * 68 + d2] = cross[n * 4096 + i];
    }
    if (t < 64) { shup[t] = upon[n * 64 + t]; shdn[t] = down[n * 64 + t]; }

    // shH rows l0-16 .. l0+143 (wrapped), float4 stores, stride 68
    {
        const float4* h4 = (const float4*)hidden;
        for (int i = t; i < 2560; i += 256) {         // 160 rows * 16 quads
            int rr = i >> 4, dq = i & 15;
            int row = (l0 - 16 + rr) & (Lc - 1);
            float4 v = h4[(((size_t)(b << 10) + row) * 16 + n) * 16 + dq];
            *(float4*)&shH[rr * 68 + dq * 4] = v;
        }
    }
    if (t < 160) shm[t] = mask[(b << 10) + ((l0 + t) & (Lc - 1))];
    __syncthreads();

    // per-row projection dots (float4, conflict-free)
    if (t < 160) {
        const float* hr = &shH[t * 68];
        float a = 0.f, c = 0.f;
#pragma unroll
        for (int dq = 0; dq < 16; ++dq) {
            float4 hv = *(const float4*)&hr[dq * 4];
            float4 up = *(const float4*)&shup[dq * 4];
            float4 dn = *(const float4*)&shdn[dq * 4];
            a += hv.x * up.x + hv.y * up.y + hv.z * up.z + hv.w * up.w;
            c += hv.x * dn.x + hv.y * dn.y + hv.z * dn.z + hv.w * dn.w;
        }
        su[t] = a; sd[t] = c;
    }
    __syncthreads();

    const int w = t >> 5, lane = t & 31;
    float* qcw = &qcs[w * 256];
    float* prw = &prs[w * 68];

    for (int g = 0; g < 4; ++g) {
        const int lloc0 = w * 16 + g * 4;   // 4 consecutive l's per group
        const int rb    = lloc0 + 16;       // shH row of first l

        // Phase A: qc[i][h] for 4 l's; lane owns h=lane, h=lane+32.
        float a0[4] = {0,0,0,0}, a1[4] = {0,0,0,0};
#pragma unroll
        for (int dq = 0; dq < 16; ++dq) {
            float4 c0 = *(const float4*)&shC[lane * 68 + dq * 4];
            float4 c1 = *(const float4*)&shC[(lane + 32) * 68 + dq * 4];
#pragma unroll
            for (int i = 0; i < 4; ++i) {
                float4 hd = *(const float4*)&shH[(rb + i) * 68 + dq * 4];
                a0[i] += hd.x * c0.x + hd.y * c0.y + hd.z * c0.z + hd.w * c0.w;
                a1[i] += hd.x * c1.x + hd.y * c1.y + hd.z * c1.z + hd.w * c1.w;
            }
        }
#pragma unroll
        for (int i = 0; i < 4; ++i) {
            qcw[i * 64 + lane]      = a0[i];
            qcw[i * 64 + lane + 32] = a1[i];
        }
        __syncwarp();

        // Phase B: 17 distinct window products per l (lanes 0..16)
        if (lane < 17) {
            float p[4] = {0,0,0,0};
#pragma unroll
            for (int hq = 0; hq < 16; ++hq) {
#pragma unroll
                for (int i = 0; i < 4; ++i) {
                    float4 qv = *(const float4*)&qcw[i * 64 + hq * 4];
                    float4 hv = *(const float4*)&shH[(rb + i + lane) * 68 + hq * 4];
                    p[i] += qv.x * hv.x + qv.y * hv.y + qv.z * hv.z + qv.w * hv.w;
                }
            }
#pragma unroll
            for (int i = 0; i < 4; ++i) prw[i * 17 + lane] = p[i];
        }
        __syncwarp();

        // Output: assemble 33 scores per l from 17 products
#pragma unroll
        for (int i = 0; i < 4; ++i) {
            const int lloc = lloc0 + i, l = l0 + lloc, rbl = rb + i;
            size_t obase = ((size_t)((b * 16 + n) * Lc + l)) * 33;
#pragma unroll
            for (int vi = 0; vi < 2; ++vi) {
                int v = lane + vi * 32;
                if (v < 33) {
                    int offu = (v <= 16) ? 0 : (v - 16);
                    int offd = (v <  16) ? (v - 16) : 0;
                    float sc = prw[i * 17 + offu] + su[rbl + offu] + sd[rbl + offd];
                    sc = (sc > 0.f) ? sc : 5.0f * sc;       // leaky_relu slope 5
                    bool m = (l + offd >= 0) && (l + offu < Lc) &&
                             (shm[lloc + offu] != 0);
                    out_ws[obase + v] = m ? sc : MASK_FILL;
                }
            }
        }
        __syncwarp();   // qcw/prw reused next group
    }
}

extern "C" void kernel_launch(void* const* d_in, const int* in_sizes, int n_in,
                              void* d_out, int out_size) {
    const float* hidden = (const float*)d_in[0];
    const int*   mask   = (const int*)d_in[1];      // bool -> int32 on the wire
    const float* upon   = (const float*)d_in[2];
    const float* down   = (const float*)d_in[3];
    const float* cross  = (const float*)d_in[4];
    // d_in[5] (window_size) fixed at 16; compiled in.

    float*  out_ws  = (float*)d_out;
    float4* out_val = (float4*)(out_ws + (size_t)4 * 16 * Lc * 33); // 2,162,688 floats

    const int smem = 18432 * (int)sizeof(float);    // 73,728 B (both paths)
    cudaFuncSetAttribute(fused_kernel, cudaFuncAttributeMaxDynamicSharedMemorySize, smem);

    // 2560 blocks: 512 score (bid%5==0) interleaved with 2048 value blocks
    fused_kernel<<<2560, 256, smem>>>(hidden, mask, upon, down, cross,
                                      out_ws, out_val);
}

// round 9
// speedup vs baseline: 1.5012x; 1.0664x over previous
#include <cuda_runtime.h>

// EdgeBlock fused: windowed scoring + value gather, single kernel launch.
// B=4, L=1024, N=16, D=64, W=16, V=33.
//
// Outputs (concatenated fp32 in d_out):
//   window_score (B,N,L,V)    = 2,162,688 floats
//   value_h      (B,L,V,N,D)  = 138,412,032 floats (553 MB, DRAM-write bound)
//
// R8 lesson: occupancy was NOT the store-feed lever (33% occ -> still 49%
// DRAM). The regression vs the standalone value kernel (72.7% DRAM) came from
// shrinking value tiles 8-l -> 2-l (read amp 3 -> 9 rows/l). This round
// restores the PROVEN value config exactly (8-l tiles, 24 staged rows, 96 KB
// smem, 2 CTAs/SM) and fuses by block ORDER: 512 long value blocks first,
// 512 short score blocks last to pack the value tail wave (512/296 = 1.73
// waves). Output stores use __stcs so the 553 MB stream doesn't evict hidden
// (16 MB, L2-resident) from L2.

#define Lc 1024
#define MASK_FILL -1e12f

__global__ void __launch_bounds__(256, 2) fused_kernel(
    const float* __restrict__ hidden,
    const int*   __restrict__ mask,
    const float* __restrict__ upon,
    const float* __restrict__ down,
    const float* __restrict__ cross,
    float*       __restrict__ out_ws,
    float4*      __restrict__ out_val)
{
    extern __shared__ float sm[];
    const int t   = threadIdx.x;
    const int bid = blockIdx.x;

    if (bid < 512) {
        // ------------- value path: 8-l tile, 24 staged rows (96 KB) -------------
        // Exact config that measured 5764 GB/s standalone.
        float4* sh4 = (float4*)sm;
        const int b  = bid >> 7;            // 0..3
        const int l0 = (bid & 127) * 8;
        const float4* hidden4 = (const float4*)hidden;

#pragma unroll
        for (int r = 0; r < 24; ++r) {
            int row = (l0 + r) & (Lc - 1);
            sh4[r * 256 + t] = hidden4[((size_t)(b << 10) + row) * 256 + t];
        }
        __syncthreads();

        for (int ll = 0; ll < 8; ++ll) {
            size_t base = ((size_t)((b << 10) + l0 + ll)) * 33 * 256 + t;
#pragma unroll
            for (int v = 0; v < 33; ++v) {
                int off = (v <= 16) ? 0 : (v - 16);
                __stcs(&out_val[base + (size_t)v * 256], sh4[(ll + off) * 256 + t]);
            }
        }
        return;
    }

    // ------------------------- score path: s in 0..511 -------------------------
    const int s = bid - 512;
    const int tile = s & 7, n = (s >> 3) & 15, b = s >> 7;
    const int l0 = tile * 128;

    float* shC  = sm;             // [64][68]  (cross transposed: shC[h*68+d])
    float* shH  = sm + 4352;      // [160][68] (rows l0-16 .. l0+143, wrapped)
    float* su   = sm + 15232;     // [160]
    float* sd   = sm + 15392;     // [160]
    float* shup = sm + 15552;     // [64]
    float* shdn = sm + 15616;     // [64]
    float* qcs  = sm + 15680;     // [8][4][64] per-warp qc buffer
    float* prs  = sm + 17728;     // [8][4][17] per-warp prod buffer
    int*   shm  = (int*)(sm + 18272); // [160]

    // cross transposed: shC[h][d] = cross[n][d][h]
    for (int i = t; i < 4096; i += 256) {
        int d2 = i >> 6, h2 = i & 63;
        shC[h2 * 68 + d2] = cross[n * 4096 + i];
    }
    if (t < 64) { shup[t] = upon[n * 64 + t]; shdn[t] = down[n * 64 + t]; }

    // shH rows l0-16 .. l0+143 (wrapped), float4 stores, stride 68
    {
        const float4* h4 = (const float4*)hidden;
        for (int i = t; i < 2560; i += 256) {         // 160 rows * 16 quads
            int rr = i >> 4, dq = i & 15;
            int row = (l0 - 16 + rr) & (Lc - 1);
            float4 v = h4[(((size_t)(b << 10) + row) * 16 + n) * 16 + dq];
            *(float4*)&shH[rr * 68 + dq * 4] = v;
        }
    }
    if (t < 160) shm[t] = mask[(b << 10) + ((l0 + t) & (Lc - 1))];
    __syncthreads();

    // per-row projection dots (float4, conflict-free)
    if (t < 160) {
        const float* hr = &shH[t * 68];
        float a = 0.f, c = 0.f;
#pragma unroll
        for (int dq = 0; dq < 16; ++dq) {
            float4 hv = *(const float4*)&hr[dq * 4];
            float4 up = *(const float4*)&shup[dq * 4];
            float4 dn = *(const float4*)&shdn[dq * 4];
            a += hv.x * up.x + hv.y * up.y + hv.z * up.z + hv.w * up.w;
            c += hv.x * dn.x + hv.y * dn.y + hv.z * dn.z + hv.w * dn.w;
        }
        su[t] = a; sd[t] = c;
    }
    __syncthreads();

    const int w = t >> 5, lane = t & 31;
    float* qcw = &qcs[w * 256];
    float* prw = &prs[w * 68];

    for (int g = 0; g < 4; ++g) {
        const int lloc0 = w * 16 + g * 4;   // 4 consecutive l's per group
        const int rb    = lloc0 + 16;       // shH row of first l

        // Phase A: qc[i][h] for 4 l's; lane owns h=lane, h=lane+32.
        float a0[4] = {0,0,0,0}, a1[4] = {0,0,0,0};
#pragma unroll
        for (int dq = 0; dq < 16; ++dq) {
            float4 c0 = *(const float4*)&shC[lane * 68 + dq * 4];
            float4 c1 = *(const float4*)&shC[(lane + 32) * 68 + dq * 4];
#pragma unroll
            for (int i = 0; i < 4; ++i) {
                float4 hd = *(const float4*)&shH[(rb + i) * 68 + dq * 4];
                a0[i] += hd.x * c0.x + hd.y * c0.y + hd.z * c0.z + hd.w * c0.w;
                a1[i] += hd.x * c1.x + hd.y * c1.y + hd.z * c1.z + hd.w * c1.w;
            }
        }
#pragma unroll
        for (int i = 0; i < 4; ++i) {
            qcw[i * 64 + lane]      = a0[i];
            qcw[i * 64 + lane + 32] = a1[i];
        }
        __syncwarp();

        // Phase B: 17 distinct window products per l (lanes 0..16)
        if (lane < 17) {
            float p[4] = {0,0,0,0};
#pragma unroll
            for (int hq = 0; hq < 16; ++hq) {
#pragma unroll
                for (int i = 0; i < 4; ++i) {
                    float4 qv = *(const float4*)&qcw[i * 64 + hq * 4];
                    float4 hv = *(const float4*)&shH[(rb + i + lane) * 68 + hq * 4];
                    p[i] += qv.x * hv.x + qv.y * hv.y + qv.z * hv.z + qv.w * hv.w;
                }
            }
#pragma unroll
            for (int i = 0; i < 4; ++i) prw[i * 17 + lane] = p[i];
        }
        __syncwarp();

        // Output: assemble 33 scores per l from 17 products
#pragma unroll
        for (int i = 0; i < 4; ++i) {
            const int lloc = lloc0 + i, l = l0 + lloc, rbl = rb + i;
            size_t obase = ((size_t)((b * 16 + n) * Lc + l)) * 33;
#pragma unroll
            for (int vi = 0; vi < 2; ++vi) {
                int v = lane + vi * 32;
                if (v < 33) {
                    int offu = (v <= 16) ? 0 : (v - 16);
                    int offd = (v <  16) ? (v - 16) : 0;
                    float sc = prw[i * 17 + offu] + su[rbl + offu] + sd[rbl + offd];
                    sc = (sc > 0.f) ? sc : 5.0f * sc;       // leaky_relu slope 5
                    bool m = (l + offd >= 0) && (l + offu < Lc) &&
                             (shm[lloc + offu] != 0);
                    __stcs(&out_ws[obase + v], m ? sc : MASK_FILL);
                }
            }
        }
        __syncwarp();   // qcw/prw reused next group
    }
}

extern "C" void kernel_launch(void* const* d_in, const int* in_sizes, int n_in,
                              void* d_out, int out_size) {
    const float* hidden = (const float*)d_in[0];
    const int*   mask   = (const int*)d_in[1];      // bool -> int32 on the wire
    const float* upon   = (const float*)d_in[2];
    const float* down   = (const float*)d_in[3];
    const float* cross  = (const float*)d_in[4];
    // d_in[5] (window_size) fixed at 16; compiled in.

    float*  out_ws  = (float*)d_out;
    float4* out_val = (float4*)(out_ws + (size_t)4 * 16 * Lc * 33); // 2,162,688 floats

    const int smem = 24 * 256 * (int)sizeof(float4);   // 98,304 B (value path max)
    cudaFuncSetAttribute(fused_kernel, cudaFuncAttributeMaxDynamicSharedMemorySize, smem);

    // 1024 blocks: bid<512 value (long, BW-bound, start first),
    //              bid>=512 score (short, packs the value tail wave)
    fused_kernel<<<1024, 256, smem>>>(hidden, mask, upon, down, cross,
                                      out_ws, out_val);
}

// round 10
// speedup vs baseline: 1.6400x; 1.0925x over previous
#include <cuda_runtime.h>

// EdgeBlock fused: windowed scoring + value gather, single kernel launch.
// B=4, L=1024, N=16, D=64, W=16, V=33.
//
// Outputs (concatenated fp32 in d_out):
//   window_score (B,N,L,V)    = 2,162,688 floats
//   value_h      (B,L,V,N,D)  = 138,412,032 floats (553 MB, DRAM-write bound)
//
// R9 post-mortem: DRAM-busy time in the fused kernel (65.8us) == standalone
// value kernel (64.3us) -> value phase is at full efficiency; the loss is a
// ~40us SERIAL score tail with DRAM idle (512 score CTAs = 1.73 waves of
// their own after the value waves drain). Fix: 1:1 block interleave
// (bid&1: even=value, odd=score) so the smem-bound score CTAs (~30us total
// per-SM crossbar time, near-zero DRAM: hidden is L2-resident) hide UNDER the
// 100us DRAM write stream. Value config unchanged from its proven 5764 GB/s
// form: 8-l tiles, 24 staged rows, 96 KB smem, 2 CTAs/SM, __stcs stores.

#define Lc 1024
#define MASK_FILL -1e12f

__global__ void __launch_bounds__(256, 2) fused_kernel(
    const float* __restrict__ hidden,
    const int*   __restrict__ mask,
    const float* __restrict__ upon,
    const float* __restrict__ down,
    const float* __restrict__ cross,
    float*       __restrict__ out_ws,
    float4*      __restrict__ out_val)
{
    extern __shared__ float sm[];
    const int t   = threadIdx.x;
    const int bid = blockIdx.x;
    const int s   = bid >> 1;               // 0..511 within each class

    if ((bid & 1) == 0) {
        // ------------- value path: 8-l tile, 24 staged rows (96 KB) -------------
        float4* sh4 = (float4*)sm;
        const int b  = s >> 7;               // 0..3
        const int l0 = (s & 127) * 8;
        const float4* hidden4 = (const float4*)hidden;

#pragma unroll
        for (int r = 0; r < 24; ++r) {
            int row = (l0 + r) & (Lc - 1);
            sh4[r * 256 + t] = hidden4[((size_t)(b << 10) + row) * 256 + t];
        }
        __syncthreads();

        for (int ll = 0; ll < 8; ++ll) {
            size_t base = ((size_t)((b << 10) + l0 + ll)) * 33 * 256 + t;
#pragma unroll
            for (int v = 0; v < 33; ++v) {
                int off = (v <= 16) ? 0 : (v - 16);
                __stcs(&out_val[base + (size_t)v * 256], sh4[(ll + off) * 256 + t]);
            }
        }
        return;
    }

    // ------------------------- score path: s in 0..511 -------------------------
    const int tile = s & 7, n = (s >> 3) & 15, b = s >> 7;
    const int l0 = tile * 128;

    float* shC  = sm;             // [64][68]  (cross transposed: shC[h*68+d])
    float* shH  = sm + 4352;      // [160][68] (rows l0-16 .. l0+143, wrapped)
    float* su   = sm + 15232;     // [160]
    float* sd   = sm + 15392;     // [160]
    float* shup = sm + 15552;     // [64]
    float* shdn = sm + 15616;     // [64]
    float* qcs  = sm + 15680;     // [8][4][64] per-warp qc buffer
    float* prs  = sm + 17728;     // [8][4][17] per-warp prod buffer
    int*   shm  = (int*)(sm + 18272); // [160]

    // cross transposed: shC[h][d] = cross[n][d][h]
    for (int i = t; i < 4096; i += 256) {
        int d2 = i >> 6, h2 = i & 63;
        shC[h2 * 68 + d2] = cross[n * 4096 + i];
    }
    if (t < 64) { shup[t] = upon[n * 64 + t]; shdn[t] = down[n * 64 + t]; }

    // shH rows l0-16 .. l0+143 (wrapped), float4 stores, stride 68
    {
        const float4* h4 = (const float4*)hidden;
        for (int i = t; i < 2560; i += 256) {         // 160 rows * 16 quads
            int rr = i >> 4, dq = i & 15;
            int row = (l0 - 16 + rr) & (Lc - 1);
            float4 v = h4[(((size_t)(b << 10) + row) * 16 + n) * 16 + dq];
            *(float4*)&shH[rr * 68 + dq * 4] = v;
        }
    }
    if (t < 160) shm[t] = mask[(b << 10) + ((l0 + t) & (Lc - 1))];
    __syncthreads();

    // per-row projection dots (float4, conflict-free)
    if (t < 160) {
        const float* hr = &shH[t * 68];
        float a = 0.f, c = 0.f;
#pragma unroll
        for (int dq = 0; dq < 16; ++dq) {
            float4 hv = *(const float4*)&hr[dq * 4];
            float4 up = *(const float4*)&shup[dq * 4];
            float4 dn = *(const float4*)&shdn[dq * 4];
            a += hv.x * up.x + hv.y * up.y + hv.z * up.z + hv.w * up.w;
            c += hv.x * dn.x + hv.y * dn.y + hv.z * dn.z + hv.w * dn.w;
        }
        su[t] = a; sd[t] = c;
    }
    __syncthreads();

    const int w = t >> 5, lane = t & 31;
    float* qcw = &qcs[w * 256];
    float* prw = &prs[w * 68];

    for (int g = 0; g < 4; ++g) {
        const int lloc0 = w * 16 + g * 4;   // 4 consecutive l's per group
        const int rb    = lloc0 + 16;       // shH row of first l

        // Phase A: qc[i][h] for 4 l's; lane owns h=lane, h=lane+32.
        float a0[4] = {0,0,0,0}, a1[4] = {0,0,0,0};
#pragma unroll
        for (int dq = 0; dq < 16; ++dq) {
            float4 c0 = *(const float4*)&shC[lane * 68 + dq * 4];
            float4 c1 = *(const float4*)&shC[(lane + 32) * 68 + dq * 4];
#pragma unroll
            for (int i = 0; i < 4; ++i) {
                float4 hd = *(const float4*)&shH[(rb + i) * 68 + dq * 4];
                a0[i] += hd.x * c0.x + hd.y * c0.y + hd.z * c0.z + hd.w * c0.w;
                a1[i] += hd.x * c1.x + hd.y * c1.y + hd.z * c1.z + hd.w * c1.w;
            }
        }
#pragma unroll
        for (int i = 0; i < 4; ++i) {
            qcw[i * 64 + lane]      = a0[i];
            qcw[i * 64 + lane + 32] = a1[i];
        }
        __syncwarp();

        // Phase B: 17 distinct window products per l (lanes 0..16)
        if (lane < 17) {
            float p[4] = {0,0,0,0};
#pragma unroll
            for (int hq = 0; hq < 16; ++hq) {
#pragma unroll
                for (int i = 0; i < 4; ++i) {
                    float4 qv = *(const float4*)&qcw[i * 64 + hq * 4];
                    float4 hv = *(const float4*)&shH[(rb + i + lane) * 68 + hq * 4];
                    p[i] += qv.x * hv.x + qv.y * hv.y + qv.z * hv.z + qv.w * hv.w;
                }
            }
#pragma unroll
            for (int i = 0; i < 4; ++i) prw[i * 17 + lane] = p[i];
        }
        __syncwarp();

        // Output: assemble 33 scores per l from 17 products
#pragma unroll
        for (int i = 0; i < 4; ++i) {
            const int lloc = lloc0 + i, l = l0 + lloc, rbl = rb + i;
            size_t obase = ((size_t)((b * 16 + n) * Lc + l)) * 33;
#pragma unroll
            for (int vi = 0; vi < 2; ++vi) {
                int v = lane + vi * 32;
                if (v < 33) {
                    int offu = (v <= 16) ? 0 : (v - 16);
                    int offd = (v <  16) ? (v - 16) : 0;
                    float sc = prw[i * 17 + offu] + su[rbl + offu] + sd[rbl + offd];
                    sc = (sc > 0.f) ? sc : 5.0f * sc;       // leaky_relu slope 5
                    bool m = (l + offd >= 0) && (l + offu < Lc) &&
                             (shm[lloc + offu] != 0);
                    __stcs(&out_ws[obase + v], m ? sc : MASK_FILL);
                }
            }
        }
        __syncwarp();   // qcw/prw reused next group
    }
}

extern "C" void kernel_launch(void* const* d_in, const int* in_sizes, int n_in,
                              void* d_out, int out_size) {
    const float* hidden = (const float*)d_in[0];
    const int*   mask   = (const int*)d_in[1];      // bool -> int32 on the wire
    const float* upon   = (const float*)d_in[2];
    const float* down   = (const float*)d_in[3];
    const float* cross  = (const float*)d_in[4];
    // d_in[5] (window_size) fixed at 16; compiled in.

    float*  out_ws  = (float*)d_out;
    float4* out_val = (float4*)(out_ws + (size_t)4 * 16 * Lc * 33); // 2,162,688 floats

    const int smem = 24 * 256 * (int)sizeof(float4);   // 98,304 B (value path max)
    cudaFuncSetAttribute(fused_kernel, cudaFuncAttributeMaxDynamicSharedMemorySize, smem);

    // 1024 blocks, 1:1 interleave: even bid = value, odd bid = score.
    // Score CTAs (smem-bound, ~zero DRAM) hide under the DRAM write stream.
    fused_kernel<<<1024, 256, smem>>>(hidden, mask, upon, down, cross,
                                      out_ws, out_val);
}